// round 15
// baseline (speedup 1.0000x reference)
#include <cuda_runtime.h>
#include <math.h>

#define NMAT 256
#define D 64
#define DD 4096          // 64*64
#define DQ 68            // padded row stride (float4-aligned)
#define NSWEEP_OS 7      // one-sided Jacobi sweeps (6 fails @1.9e-3, 8 proven 1.3e-5)

// ---------------- device scratch (no allocations allowed) ----------------
__device__ float g_L[NMAT * DD];          // log(X) matrices        (4 MB)
__device__ float g_S[NMAT * DD];          // log(X) + M             (4 MB)
__device__ float g_gp[8 * NMAT * NMAT];   // split-K gram partials  (2 MB)
__device__ float g_W[NMAT * NMAT];        // kernel weights         (256 KB)
__device__ float g_sq[NMAT];
__device__ float g_s[NMAT];
__device__ float g_rs[NMAT];              // row sums
__device__ float g_cs[NMAT];              // col sums

// ========================================================================
// Kernel 1: one-sided Jacobi log, TWO matrices per 64-thread CTA,
//   BOTH matrices interleaved in each warp's instruction stream (two
//   independent latency chains fill each other's stalls). Warp h holds
//   elements [32h,32h+32) of column pair (2l,2l+1) for both matrices.
//   Tangent-form rotations, division/branch-free. One __syncthreads per
//   round serves both matrices (double-buffered partial-dot exchange).
//   Per-matrix numerics identical to the R12 kernel.
// ========================================================================
__global__ __launch_bounds__(64) void onesided_log_kernel(const float* __restrict__ X) {
    __shared__ float Gsm[2][D * DQ];       // per-slot columns
    __shared__ float wcol[2][D];           // per-slot per-column log-weights
    __shared__ float pdot[2][2][2][32];    // [buf][slot][half][lane]
    __shared__ float2 pnorm[2][2][32];     // [slot][half][lane]
    __shared__ float reds[2][2], redq[2][2];

    const int tid  = threadIdx.x;
    const int h    = tid >> 5;             // element half
    const int ow   = h ^ 1;
    const int lane = tid & 31;
    const unsigned FULL = 0xffffffffu;
    const int m0 = 2 * blockIdx.x, m1 = m0 + 1;

    float a0[32], b0[32], a1[32], b1[32];

    // X symmetric: column c == row c. Load element half for both matrices.
    {
        const float4* ra0 = (const float4*)(X + (size_t)m0 * DD + (2 * lane)     * D + 32 * h);
        const float4* rb0 = (const float4*)(X + (size_t)m0 * DD + (2 * lane + 1) * D + 32 * h);
        const float4* ra1 = (const float4*)(X + (size_t)m1 * DD + (2 * lane)     * D + 32 * h);
        const float4* rb1 = (const float4*)(X + (size_t)m1 * DD + (2 * lane + 1) * D + 32 * h);
        #pragma unroll
        for (int t = 0; t < 8; ++t) {
            float4 v0 = ra0[t];
            a0[4*t+0] = v0.x; a0[4*t+1] = v0.y; a0[4*t+2] = v0.z; a0[4*t+3] = v0.w;
            float4 u0 = rb0[t];
            b0[4*t+0] = u0.x; b0[4*t+1] = u0.y; b0[4*t+2] = u0.z; b0[4*t+3] = u0.w;
            float4 v1 = ra1[t];
            a1[4*t+0] = v1.x; a1[4*t+1] = v1.y; a1[4*t+2] = v1.z; a1[4*t+3] = v1.w;
            float4 u1 = rb1[t];
            b1[4*t+0] = u1.x; b1[4*t+1] = u1.y; b1[4*t+2] = u1.z; b1[4*t+3] = u1.w;
        }
    }

    // initial full norms via partial exchange (both slots, one barrier)
    float na0, nb0, sa0 = 1.f, sb0 = 1.f, isa0 = 1.f, isb0 = 1.f;
    float na1, nb1, sa1 = 1.f, sb1 = 1.f, isa1 = 1.f, isb1 = 1.f;
    {
        float p0 = 0.f, q0 = 0.f, p1 = 0.f, q1 = 0.f;
        #pragma unroll
        for (int k = 0; k < 32; ++k) {
            p0 = fmaf(a0[k], a0[k], p0);  q0 = fmaf(b0[k], b0[k], q0);
            p1 = fmaf(a1[k], a1[k], p1);  q1 = fmaf(b1[k], b1[k], q1);
        }
        pnorm[0][h][lane] = make_float2(p0, q0);
        pnorm[1][h][lane] = make_float2(p1, q1);
        __syncthreads();
        float2 o0 = pnorm[0][ow][lane];
        float2 o1 = pnorm[1][ow][lane];
        na0 = p0 + o0.x; nb0 = q0 + o0.y;
        na1 = p1 + o1.x; nb1 = q1 + o1.y;
    }

    int pb = 0;
    for (int sw = 0; sw < NSWEEP_OS; ++sw) {
        for (int rr = 0; rr < 63; ++rr) {
            // partial cross dots, both slots (independent chains)
            float g00 = 0.f, g01 = 0.f, g10 = 0.f, g11 = 0.f;
            #pragma unroll
            for (int k = 0; k < 32; k += 2) {
                g00 = fmaf(a0[k+0], b0[k+0], g00);
                g01 = fmaf(a0[k+1], b0[k+1], g01);
                g10 = fmaf(a1[k+0], b1[k+0], g10);
                g11 = fmaf(a1[k+1], b1[k+1], g11);
            }
            float gp0 = g00 + g01, gp1 = g10 + g11;
            pdot[pb][0][h][lane] = gp0;
            pdot[pb][1][h][lane] = gp1;
            __syncthreads();
            float ghat0 = gp0 + pdot[pb][0][ow][lane];
            float ghat1 = gp1 + pdot[pb][1][ow][lane];
            pb ^= 1;

            // --- slot 0 scalar chain ---
            float gam0 = sa0 * sb0 * ghat0;
            float tau0 = (nb0 - na0) * __fdividef(0.5f, gam0);
            tau0 = fminf(fmaxf(tau0, -1e18f), 1e18f);
            float opt20 = fmaf(tau0, tau0, 1.0f);
            float sq0   = opt20 * rsqrtf(opt20);
            float tt0   = copysignf(__fdividef(1.0f, fabsf(tau0) + sq0), tau0);
            float c20   = fmaf(tt0, tt0, 1.0f);
            float c0    = rsqrtf(c20);
            float ic0   = c20 * c0;
            float s0    = tt0 * c0;
            float u0 = tt0 * sb0 * isa0;
            float v0 = tt0 * sa0 * isb0;

            // --- slot 1 scalar chain (independent) ---
            float gam1 = sa1 * sb1 * ghat1;
            float tau1 = (nb1 - na1) * __fdividef(0.5f, gam1);
            tau1 = fminf(fmaxf(tau1, -1e18f), 1e18f);
            float opt21 = fmaf(tau1, tau1, 1.0f);
            float sq1   = opt21 * rsqrtf(opt21);
            float tt1   = copysignf(__fdividef(1.0f, fabsf(tau1) + sq1), tau1);
            float c21   = fmaf(tt1, tt1, 1.0f);
            float c1    = rsqrtf(c21);
            float ic1   = c21 * c1;
            float s1    = tt1 * c1;
            float u1 = tt1 * sb1 * isa1;
            float v1 = tt1 * sa1 * isb1;

            // rotate both (independent FMA streams)
            #pragma unroll
            for (int k = 0; k < 32; ++k) {
                float av0 = a0[k], bv0 = b0[k];
                a0[k] = fmaf(-u0, bv0, av0);
                b0[k] = fmaf( v0, av0, bv0);
                float av1 = a1[k], bv1 = b1[k];
                a1[k] = fmaf(-u1, bv1, av1);
                b1[k] = fmaf( v1, av1, bv1);
            }
            sa0 *= c0; sb0 *= c0; isa0 *= ic0; isb0 *= ic0;
            sa1 *= c1; sb1 *= c1; isa1 *= ic1; isb1 *= ic1;

            // true-norm tracking (exact rotation identities)
            {
                float csg = 2.0f * c0 * s0 * gam0;
                float cc2 = c0 * c0, ss2 = s0 * s0;
                float nn = cc2 * na0 + ss2 * nb0 - csg;
                nb0 = ss2 * na0 + cc2 * nb0 + csg;
                na0 = nn;
            }
            {
                float csg = 2.0f * c1 * s1 * gam1;
                float cc2 = c1 * c1, ss2 = s1 * s1;
                float nn = cc2 * na1 + ss2 * nb1 - csg;
                nb1 = ss2 * na1 + cc2 * nb1 + csg;
                na1 = nn;
            }

            // Brent-Luk permutation: scalars (both slots)
            {
                float tn, up, dn, o;
                o = na0; tn = (lane == 0) ? nb0 : na0;
                up = __shfl_up_sync(FULL, tn, 1);
                dn = __shfl_down_sync(FULL, nb0, 1);
                na0 = (lane == 0) ? o : up;  nb0 = (lane == 31) ? o : dn;

                o = na1; tn = (lane == 0) ? nb1 : na1;
                up = __shfl_up_sync(FULL, tn, 1);
                dn = __shfl_down_sync(FULL, nb1, 1);
                na1 = (lane == 0) ? o : up;  nb1 = (lane == 31) ? o : dn;

                o = sa0; tn = (lane == 0) ? sb0 : sa0;
                up = __shfl_up_sync(FULL, tn, 1);
                dn = __shfl_down_sync(FULL, sb0, 1);
                sa0 = (lane == 0) ? o : up;  sb0 = (lane == 31) ? o : dn;

                o = sa1; tn = (lane == 0) ? sb1 : sa1;
                up = __shfl_up_sync(FULL, tn, 1);
                dn = __shfl_down_sync(FULL, sb1, 1);
                sa1 = (lane == 0) ? o : up;  sb1 = (lane == 31) ? o : dn;

                o = isa0; tn = (lane == 0) ? isb0 : isa0;
                up = __shfl_up_sync(FULL, tn, 1);
                dn = __shfl_down_sync(FULL, isb0, 1);
                isa0 = (lane == 0) ? o : up;  isb0 = (lane == 31) ? o : dn;

                o = isa1; tn = (lane == 0) ? isb1 : isa1;
                up = __shfl_up_sync(FULL, tn, 1);
                dn = __shfl_down_sync(FULL, isb1, 1);
                isa1 = (lane == 0) ? o : up;  isb1 = (lane == 31) ? o : dn;
            }
            // Brent-Luk permutation: elements (interleaved slots)
            #pragma unroll
            for (int k = 0; k < 32; ++k) {
                float oa0  = a0[k];
                float tmp0 = (lane == 0) ? b0[k] : oa0;
                float up0  = __shfl_up_sync(FULL, tmp0, 1);
                float dn0  = __shfl_down_sync(FULL, b0[k], 1);
                a0[k] = (lane == 0)  ? oa0 : up0;
                b0[k] = (lane == 31) ? oa0 : dn0;

                float oa1  = a1[k];
                float tmp1 = (lane == 0) ? b1[k] : oa1;
                float up1  = __shfl_up_sync(FULL, tmp1, 1);
                float dn1  = __shfl_down_sync(FULL, b1[k], 1);
                a1[k] = (lane == 0)  ? oa1 : up1;
                b1[k] = (lane == 31) ? oa1 : dn1;
            }
        }

        // per-sweep renormalization (both slots)
        #pragma unroll
        for (int k = 0; k < 32; ++k) {
            a0[k] *= sa0; b0[k] *= sb0;
            a1[k] *= sa1; b1[k] *= sb1;
        }
        sa0 = sb0 = isa0 = isb0 = 1.0f;
        sa1 = sb1 = isa1 = isb1 = 1.0f;
    }

    // exact final norms via partial exchange (both slots, one barrier)
    {
        float p0 = 0.f, q0 = 0.f, p1 = 0.f, q1 = 0.f;
        #pragma unroll
        for (int k = 0; k < 32; ++k) {
            p0 = fmaf(a0[k], a0[k], p0);  q0 = fmaf(b0[k], b0[k], q0);
            p1 = fmaf(a1[k], a1[k], p1);  q1 = fmaf(b1[k], b1[k], q1);
        }
        pnorm[0][h][lane] = make_float2(p0, q0);
        pnorm[1][h][lane] = make_float2(p1, q1);
        __syncthreads();
        float2 o0 = pnorm[0][ow][lane];
        float2 o1 = pnorm[1][ow][lane];
        na0 = p0 + o0.x; nb0 = q0 + o0.y;
        na1 = p1 + o1.x; nb1 = q1 + o1.y;
    }

    // weight = log(lambda)/lambda^2 with lambda^2 = |g|^2
    float wa0 = 0.5f * logf(fmaxf(na0, 1e-30f)) / na0;
    float wb0 = 0.5f * logf(fmaxf(nb0, 1e-30f)) / nb0;
    float wa1 = 0.5f * logf(fmaxf(na1, 1e-30f)) / na1;
    float wb1 = 0.5f * logf(fmaxf(nb1, 1e-30f)) / nb1;

    // stash columns + per-column weights
    {
        const int ia = 2 * lane, ib = 2 * lane + 1;
        #pragma unroll
        for (int k = 0; k < 32; ++k) {
            int r = 32 * h + k;
            Gsm[0][r * DQ + ia] = a0[k];
            Gsm[0][r * DQ + ib] = b0[k];
            Gsm[1][r * DQ + ia] = a1[k];
            Gsm[1][r * DQ + ib] = b1[k];
        }
        if (h == 0) {
            wcol[0][ia] = wa0; wcol[0][ib] = wb0;
            wcol[1][ia] = wa1; wcol[1][ib] = wb1;
        }
    }
    __syncthreads();

    // L[r,c] = sum_col wcol[col]*G[r,col]*G[c,col]; thread -> row tid, slots 0,1
    #pragma unroll
    for (int q = 0; q < 2; ++q) {
        const int mq = m0 + q;
        const int r  = tid;
        float hrow[64];
        #pragma unroll
        for (int t = 0; t < 16; ++t) {
            float4 g4 = *(const float4*)&Gsm[q][r * DQ + 4 * t];
            float4 w4 = *(const float4*)&wcol[q][4 * t];
            hrow[4*t+0] = g4.x * w4.x; hrow[4*t+1] = g4.y * w4.y;
            hrow[4*t+2] = g4.z * w4.z; hrow[4*t+3] = g4.w * w4.w;
        }

        float ssum = 0.f, sqsum = 0.f;
        float* orow = g_L + (size_t)mq * DD + r * D;
        for (int c4 = 0; c4 < D; c4 += 4) {
            float acc[4] = {0.f, 0.f, 0.f, 0.f};
            #pragma unroll
            for (int cc = 0; cc < 4; ++cc) {
                const int c = c4 + cc;
                #pragma unroll
                for (int t = 0; t < 16; ++t) {
                    float4 g = *(const float4*)&Gsm[q][c * DQ + 4 * t];  // broadcast
                    acc[cc] = fmaf(hrow[4*t+0], g.x, acc[cc]);
                    acc[cc] = fmaf(hrow[4*t+1], g.y, acc[cc]);
                    acc[cc] = fmaf(hrow[4*t+2], g.z, acc[cc]);
                    acc[cc] = fmaf(hrow[4*t+3], g.w, acc[cc]);
                }
            }
            *(float4*)&orow[c4] = make_float4(acc[0], acc[1], acc[2], acc[3]);
            #pragma unroll
            for (int cc = 0; cc < 4; ++cc) {
                ssum += acc[cc];
                sqsum = fmaf(acc[cc], acc[cc], sqsum);
            }
        }
        #pragma unroll
        for (int o = 16; o; o >>= 1) {
            ssum  += __shfl_down_sync(FULL, ssum,  o);
            sqsum += __shfl_down_sync(FULL, sqsum, o);
        }
        if (lane == 0) { reds[q][h] = ssum; redq[q][h] = sqsum; }
    }
    __syncthreads();
    if (tid == 0) {
        g_s[m0]  = reds[0][0] + reds[0][1];
        g_sq[m0] = redq[0][0] + redq[0][1];
        g_s[m1]  = reds[1][0] + reds[1][1];
        g_sq[m1] = redq[1][0] + redq[1][1];
    }
}

// ========================================================================
// Kernel 2: gram partials  g_gp[z][i][j] = sum_{k in z-chunk} L[i][k] L[j][k]
// ========================================================================
__global__ __launch_bounds__(256) void gram_kernel() {
    __shared__ float As[64 * 17];
    __shared__ float Bs[64 * 17];
    const int bj = blockIdx.x, bi = blockIdx.y, bz = blockIdx.z;
    const int tid = threadIdx.x;
    const int ty = tid >> 4, tx = tid & 15;

    float acc[4][4];
    #pragma unroll
    for (int r = 0; r < 4; ++r)
        #pragma unroll
        for (int c = 0; c < 4; ++c) acc[r][c] = 0.0f;

    const int k0 = bz * 512;
    for (int kc = 0; kc < 512; kc += 16) {
        for (int l = tid; l < 1024; l += 256) {
            int r = l >> 4, kk = l & 15;
            As[r * 17 + kk] = g_L[(size_t)(bi * 64 + r) * DD + k0 + kc + kk];
            Bs[r * 17 + kk] = g_L[(size_t)(bj * 64 + r) * DD + k0 + kc + kk];
        }
        __syncthreads();
        #pragma unroll
        for (int kk = 0; kk < 16; ++kk) {
            float a[4], b[4];
            #pragma unroll
            for (int r = 0; r < 4; ++r) a[r] = As[(ty * 4 + r) * 17 + kk];
            #pragma unroll
            for (int c = 0; c < 4; ++c) b[c] = Bs[(tx * 4 + c) * 17 + kk];
            #pragma unroll
            for (int r = 0; r < 4; ++r)
                #pragma unroll
                for (int c = 0; c < 4; ++c)
                    acc[r][c] = fmaf(a[r], b[c], acc[r][c]);
        }
        __syncthreads();
    }
    #pragma unroll
    for (int r = 0; r < 4; ++r)
        #pragma unroll
        for (int c = 0; c < 4; ++c)
            g_gp[((size_t)bz * NMAT + bi * 64 + ty * 4 + r) * NMAT + bj * 64 + tx * 4 + c] = acc[r][c];
}

// ========================================================================
// Kernel 3: W = exp(-0.5 * pds / bw^2), fused row sums.  block = row i
// ========================================================================
__global__ __launch_bounds__(256) void w_kernel(const float* __restrict__ bwp) {
    __shared__ float red[8];
    const int i = blockIdx.x;
    const int j = threadIdx.x;

    float g = 0.0f;
    #pragma unroll
    for (int z = 0; z < 8; ++z)
        g += g_gp[((size_t)z * NMAT + i) * NMAT + j];

    const float bw  = bwp[0];
    const float inv = 0.5f / (bw * bw);
    const float eps = 1e-7f;
    float pds = g_sq[i] + g_sq[j] - 2.0f * g
              + 2.0f * eps * (g_s[j] - g_s[i])
              + eps * eps * 4096.0f;
    float wv = expf(-pds * inv);
    g_W[i * NMAT + j] = wv;

    float sum = wv;
    #pragma unroll
    for (int o = 16; o; o >>= 1) sum += __shfl_down_sync(0xffffffffu, sum, o);
    if ((j & 31) == 0) red[j >> 5] = sum;
    __syncthreads();
    if (j == 0) {
        float t = 0.0f;
        #pragma unroll
        for (int w = 0; w < 8; ++w) t += red[w];
        g_rs[i] = t;
    }
}

// col sums: 8 blocks x 256 threads, coalesced
__global__ __launch_bounds__(256) void colsum_kernel() {
    __shared__ float part[8][32];
    const int c0 = blockIdx.x * 32;
    const int c = threadIdx.x & 31;
    const int rchunk = threadIdx.x >> 5;
    float s = 0.0f;
    #pragma unroll
    for (int rr = 0; rr < 32; ++rr)
        s += g_W[(rchunk * 32 + rr) * NMAT + c0 + c];
    part[rchunk][c] = s;
    __syncthreads();
    if (threadIdx.x < 32) {
        float t = 0.0f;
        #pragma unroll
        for (int w = 0; w < 8; ++w) t += part[w][threadIdx.x];
        g_cs[c0 + threadIdx.x] = t;
    }
}

// ========================================================================
// Kernel 4: C = W^T L, fused mean-shift epilogue -> S = L_k + (C - cs_k L_k)/rs_k
// ========================================================================
__global__ __launch_bounds__(256) void ms_kernel() {
    __shared__ float Wt[16 * 65];
    __shared__ float Lt[16 * 65];
    const int bc = blockIdx.x;   // column tile
    const int bk = blockIdx.y;   // k (output row) tile
    const int tid = threadIdx.x;
    const int ty = tid >> 4, tx = tid & 15;

    float acc[4][4];
    #pragma unroll
    for (int r = 0; r < 4; ++r)
        #pragma unroll
        for (int c = 0; c < 4; ++c) acc[r][c] = 0.0f;

    for (int j0 = 0; j0 < NMAT; j0 += 16) {
        for (int l = tid; l < 1024; l += 256) {
            int jj = l >> 6, c = l & 63;
            Wt[jj * 65 + c] = g_W[(j0 + jj) * NMAT + bk * 64 + c];
            Lt[jj * 65 + c] = g_L[(size_t)(j0 + jj) * DD + bc * 64 + c];
        }
        __syncthreads();
        #pragma unroll
        for (int jj = 0; jj < 16; ++jj) {
            float a[4], b[4];
            #pragma unroll
            for (int r = 0; r < 4; ++r) a[r] = Wt[jj * 65 + ty * 4 + r];
            #pragma unroll
            for (int c = 0; c < 4; ++c) b[c] = Lt[jj * 65 + tx * 4 + c];
            #pragma unroll
            for (int r = 0; r < 4; ++r)
                #pragma unroll
                for (int c = 0; c < 4; ++c)
                    acc[r][c] = fmaf(a[r], b[c], acc[r][c]);
        }
        __syncthreads();
    }
    #pragma unroll
    for (int r = 0; r < 4; ++r) {
        int k = bk * 64 + ty * 4 + r;
        float rs = g_rs[k], cs = g_cs[k];
        float inv_rs = 1.0f / rs;
        #pragma unroll
        for (int c = 0; c < 4; ++c) {
            int col = bc * 64 + tx * 4 + c;
            float lk = g_L[(size_t)k * DD + col];
            g_S[(size_t)k * DD + col] = lk + (acc[r][c] - cs * lk) * inv_rs;
        }
    }
}

// ========================================================================
// Kernel 5: expm(S), scaling-and-squaring + order-8 Horner (first step folded
//   into init). 128 threads: 2 threads per row, each owns a 32-column half.
// ========================================================================
__global__ __launch_bounds__(128) void expm_kernel(float* __restrict__ out) {
    __shared__ float Q[D * DQ];
    __shared__ float redw[4];

    const int m   = blockIdx.x;
    const int tid = threadIdx.x;
    const int i   = tid >> 1;          // row
    const int c0  = (tid & 1) * 32;    // column half base

    // full B row straight from gmem (both half-threads load the same row)
    float brow[64];
    {
        const float4* sr = (const float4*)(g_S + (size_t)m * DD + i * D);
        #pragma unroll
        for (int t = 0; t < 16; ++t) {
            float4 v = sr[t];
            brow[4*t+0] = v.x; brow[4*t+1] = v.y;
            brow[4*t+2] = v.z; brow[4*t+3] = v.w;
        }
    }

    // Frobenius norm: each thread contributes its own half's squares (exact cover)
    float local = 0.0f;
    #pragma unroll
    for (int k = 0; k < 32; ++k) local = fmaf(brow[c0 + k], brow[c0 + k], local);
    #pragma unroll
    for (int o = 16; o; o >>= 1) local += __shfl_down_sync(0xffffffffu, local, o);
    if ((tid & 31) == 0) redw[tid >> 5] = local;
    __syncthreads();

    float nf = sqrtf((redw[0] + redw[1]) + (redw[2] + redw[3]));
    int ksc = 0;
    if (nf > 0.5f) {
        ksc = (int)ceilf(log2f(nf * 2.0f));
        if (ksc > 15) ksc = 15;
        if (ksc < 0)  ksc = 0;
    }
    const float sc = exp2f((float)(-ksc));
    #pragma unroll
    for (int k = 0; k < 64; ++k) brow[k] *= sc;

    // init Q = I + B/8 (folds first Horner step; order 8 total)
    {
        const float i8 = 1.0f / 8.0f;
        #pragma unroll
        for (int t = 0; t < 8; ++t) {
            int c = c0 + 4 * t;
            float4 o4 = make_float4(
                brow[c+0] * i8 + ((c+0 == i) ? 1.f : 0.f),
                brow[c+1] * i8 + ((c+1 == i) ? 1.f : 0.f),
                brow[c+2] * i8 + ((c+2 == i) ? 1.f : 0.f),
                brow[c+3] * i8 + ((c+3 == i) ? 1.f : 0.f));
            *(float4*)&Q[i * DQ + c] = o4;
        }
    }
    __syncthreads();

    float rrow[32];

    // Horner: Q_{n-1} = I + (B * Q_n)/n, n = 7..1
    for (int n = 7; n >= 1; --n) {
        #pragma unroll
        for (int j = 0; j < 32; ++j) rrow[j] = 0.0f;
        for (int k = 0; k < D; ++k) {
            float bv = brow[k];
            #pragma unroll
            for (int t = 0; t < 8; ++t) {
                float4 q = *(const float4*)&Q[k * DQ + c0 + 4 * t];
                rrow[4*t+0] = fmaf(bv, q.x, rrow[4*t+0]);
                rrow[4*t+1] = fmaf(bv, q.y, rrow[4*t+1]);
                rrow[4*t+2] = fmaf(bv, q.z, rrow[4*t+2]);
                rrow[4*t+3] = fmaf(bv, q.w, rrow[4*t+3]);
            }
        }
        __syncthreads();
        const float invn = 1.0f / (float)n;
        #pragma unroll
        for (int t = 0; t < 8; ++t) {
            int c = c0 + 4 * t;
            float4 o4 = make_float4(
                rrow[4*t+0] * invn + ((c+0 == i) ? 1.f : 0.f),
                rrow[4*t+1] * invn + ((c+1 == i) ? 1.f : 0.f),
                rrow[4*t+2] * invn + ((c+2 == i) ? 1.f : 0.f),
                rrow[4*t+3] * invn + ((c+3 == i) ? 1.f : 0.f));
            *(float4*)&Q[i * DQ + c] = o4;
        }
        __syncthreads();
    }

    // repeated squaring (ksc uniform across the block)
    for (int t2 = 0; t2 < ksc; ++t2) {
        #pragma unroll
        for (int t = 0; t < 16; ++t) {
            float4 v = *(const float4*)&Q[i * DQ + 4 * t];
            brow[4*t+0] = v.x; brow[4*t+1] = v.y; brow[4*t+2] = v.z; brow[4*t+3] = v.w;
        }
        #pragma unroll
        for (int j = 0; j < 32; ++j) rrow[j] = 0.0f;
        for (int k = 0; k < D; ++k) {
            float bv = brow[k];
            #pragma unroll
            for (int t = 0; t < 8; ++t) {
                float4 q = *(const float4*)&Q[k * DQ + c0 + 4 * t];
                rrow[4*t+0] = fmaf(bv, q.x, rrow[4*t+0]);
                rrow[4*t+1] = fmaf(bv, q.y, rrow[4*t+1]);
                rrow[4*t+2] = fmaf(bv, q.z, rrow[4*t+2]);
                rrow[4*t+3] = fmaf(bv, q.w, rrow[4*t+3]);
            }
        }
        __syncthreads();
        #pragma unroll
        for (int t = 0; t < 8; ++t)
            *(float4*)&Q[i * DQ + c0 + 4 * t] =
                make_float4(rrow[4*t+0], rrow[4*t+1], rrow[4*t+2], rrow[4*t+3]);
        __syncthreads();
    }

    float* om = out + (size_t)m * DD + i * D + c0;
    #pragma unroll
    for (int t = 0; t < 8; ++t) {
        float4 v = *(const float4*)&Q[i * DQ + c0 + 4 * t];
        *(float4*)&om[4 * t] = v;
    }
}

// ========================================================================
extern "C" void kernel_launch(void* const* d_in, const int* in_sizes, int n_in,
                              void* d_out, int out_size) {
    const float* X  = (const float*)d_in[0];
    const float* bw = (const float*)d_in[1];
    float* out = (float*)d_out;

    onesided_log_kernel<<<NMAT / 2, 64>>>(X);
    gram_kernel<<<dim3(4, 4, 8), 256>>>();
    w_kernel<<<NMAT, 256>>>(bw);
    colsum_kernel<<<8, 256>>>();
    ms_kernel<<<dim3(64, 4), 256>>>();
    expm_kernel<<<NMAT, 128>>>(out);
}

// round 16
// speedup vs baseline: 1.3174x; 1.3174x over previous
#include <cuda_runtime.h>
#include <math.h>

#define NMAT 256
#define D 64
#define DD 4096          // 64*64
#define DQ 68            // padded row stride (float4-aligned)
#define NSWEEP_OS 7      // one-sided Jacobi sweeps (6 fails @1.9e-3, 8 proven 1.3e-5)

// ---------------- device scratch (no allocations allowed) ----------------
__device__ float g_L[NMAT * DD];          // log(X) matrices        (4 MB)
__device__ float g_S[NMAT * DD];          // log(X) + M             (4 MB)
__device__ float g_gp[8 * NMAT * NMAT];   // split-K gram partials  (2 MB)
__device__ float g_W[NMAT * NMAT];        // kernel weights         (256 KB)
__device__ float g_sq[NMAT];
__device__ float g_s[NMAT];
__device__ float g_rs[NMAT];              // row sums
__device__ float g_cs[NMAT];              // col sums

// ========================================================================
// Kernel 1: one-sided Jacobi log, FOUR warps per matrix (128-thread CTA).
//   Lane l of warp w holds elements [16w,16w+16) of column pair (2l,2l+1).
//   Tangent-form rotations, division/branch-free. Cross-warp dot reduce via
//   TRANSPOSED partial array (one LDS.128 + 3 adds after one barrier);
//   all warps sum the same 4 values in the same order, so the scalar
//   rotation state stays bit-identical across warps (R12 numerics).
//   Rotate + Brent-Luk permutation merged into a single loop (FMA/SHFL
//   interleave in the issue stream).
// ========================================================================
__global__ __launch_bounds__(128) void onesided_log_kernel(const float* __restrict__ X) {
    __shared__ float Gsm[D * DQ];          // columns (Gsm[elem*DQ + col])
    __shared__ float wcol[D];              // per-column log-weights
    __shared__ float pdot[2][32][4];       // [buf][lane][warp] (transposed)
    __shared__ float pnA[32][4], pnB[32][4];
    __shared__ float reds[4], redq[4];

    const int tid  = threadIdx.x;
    const int w    = tid >> 5;             // element quarter
    const int lane = tid & 31;
    const unsigned FULL = 0xffffffffu;
    const int m = blockIdx.x;
    const float* Xm = X + (size_t)m * DD;

    float a[16], b[16];

    // X symmetric: column c == row c. Each warp loads its element quarter.
    {
        const float4* ra = (const float4*)(Xm + (2 * lane)     * D + 16 * w);
        const float4* rb = (const float4*)(Xm + (2 * lane + 1) * D + 16 * w);
        #pragma unroll
        for (int t = 0; t < 4; ++t) {
            float4 v = ra[t];
            a[4*t+0] = v.x; a[4*t+1] = v.y; a[4*t+2] = v.z; a[4*t+3] = v.w;
            float4 u = rb[t];
            b[4*t+0] = u.x; b[4*t+1] = u.y; b[4*t+2] = u.z; b[4*t+3] = u.w;
        }
    }

    // initial full norms via transposed partial exchange
    float na, nb, sa = 1.0f, sb = 1.0f, isa = 1.0f, isb = 1.0f;
    {
        float n0 = 0.f, n1 = 0.f, m0 = 0.f, m1 = 0.f;
        #pragma unroll
        for (int k = 0; k < 16; k += 2) {
            n0 = fmaf(a[k], a[k], n0);     n1 = fmaf(a[k+1], a[k+1], n1);
            m0 = fmaf(b[k], b[k], m0);     m1 = fmaf(b[k+1], b[k+1], m1);
        }
        pnA[lane][w] = n0 + n1;
        pnB[lane][w] = m0 + m1;
        __syncthreads();
        float4 va = *(const float4*)pnA[lane];
        float4 vb = *(const float4*)pnB[lane];
        na = (va.x + va.y) + (va.z + va.w);   // identical in all warps
        nb = (vb.x + vb.y) + (vb.z + vb.w);
    }

    int pb = 0;
    for (int sw = 0; sw < NSWEEP_OS; ++sw) {
        for (int rr = 0; rr < 63; ++rr) {
            // partial cross dot (2-way ILP, 8 deep)
            float g0 = 0.f, g1 = 0.f;
            #pragma unroll
            for (int k = 0; k < 16; k += 2) {
                g0 = fmaf(a[k+0], b[k+0], g0);
                g1 = fmaf(a[k+1], b[k+1], g1);
            }
            pdot[pb][lane][w] = g0 + g1;
            __syncthreads();
            float4 dv = *(const float4*)pdot[pb][lane];
            float ghat = (dv.x + dv.y) + (dv.z + dv.w);  // identical in all warps
            pb ^= 1;

            float gam = sa * sb * ghat;                  // true gamma

            // branch-free rotation params (gam==0 -> t ~ 5e-19 -> no-op)
            float tau = (nb - na) * __fdividef(0.5f, gam);
            tau = fminf(fmaxf(tau, -1e18f), 1e18f);      // NaN-safe clamp
            float opt2 = fmaf(tau, tau, 1.0f);
            float sq   = opt2 * rsqrtf(opt2);            // sqrt(1+tau^2)
            float tt   = copysignf(__fdividef(1.0f, fabsf(tau) + sq), tau);
            float c2   = fmaf(tt, tt, 1.0f);
            float c    = rsqrtf(c2);
            float ic   = c2 * c;                         // exactly 1/c
            float s    = tt * c;

            float u = tt * sb * isa;                     // a' = a - u*b
            float v = tt * sa * isb;                     // b' = b + v*a

            // merged rotate + Brent-Luk permutation
            //  a0 fixed; a1<-b0; a_i<-a_{i-1}; b_i<-b_{i+1}; b31<-a31
            #pragma unroll
            for (int k = 0; k < 16; ++k) {
                float av = a[k], bv = b[k];
                float ar = fmaf(-u, bv, av);
                float br = fmaf( v, av, bv);
                float tmp = (lane == 0) ? br : ar;
                float up  = __shfl_up_sync(FULL, tmp, 1);
                float dn  = __shfl_down_sync(FULL, br, 1);
                a[k] = (lane == 0)  ? ar : up;
                b[k] = (lane == 31) ? ar : dn;
            }
            sa *= c; sb *= c; isa *= ic; isb *= ic;

            // true-norm tracking (exact rotation identities)
            float csg = 2.0f * c * s * gam;
            float cc2 = c * c, ss2 = s * s;
            float na_n = cc2 * na + ss2 * nb - csg;
            float nb_n = ss2 * na + cc2 * nb + csg;
            na = na_n; nb = nb_n;

            // scalar permutation (replicated identically per warp)
            {
                float tn, up, dn, o;
                o = na; tn = (lane == 0) ? nb : na;
                up = __shfl_up_sync(FULL, tn, 1);
                dn = __shfl_down_sync(FULL, nb, 1);
                na = (lane == 0)  ? o : up;
                nb = (lane == 31) ? o : dn;

                o = sa; tn = (lane == 0) ? sb : sa;
                up = __shfl_up_sync(FULL, tn, 1);
                dn = __shfl_down_sync(FULL, sb, 1);
                sa = (lane == 0)  ? o : up;
                sb = (lane == 31) ? o : dn;

                o = isa; tn = (lane == 0) ? isb : isa;
                up = __shfl_up_sync(FULL, tn, 1);
                dn = __shfl_down_sync(FULL, isb, 1);
                isa = (lane == 0)  ? o : up;
                isb = (lane == 31) ? o : dn;
            }
        }

        // per-sweep renormalization (scales replicated across warps)
        #pragma unroll
        for (int k = 0; k < 16; ++k) { a[k] *= sa; b[k] *= sb; }
        sa = 1.0f; sb = 1.0f; isa = 1.0f; isb = 1.0f;
    }

    // exact final norms via transposed partial exchange
    {
        float n0 = 0.f, n1 = 0.f, m0 = 0.f, m1 = 0.f;
        #pragma unroll
        for (int k = 0; k < 16; k += 2) {
            n0 = fmaf(a[k], a[k], n0);     n1 = fmaf(a[k+1], a[k+1], n1);
            m0 = fmaf(b[k], b[k], m0);     m1 = fmaf(b[k+1], b[k+1], m1);
        }
        pnA[lane][w] = n0 + n1;
        pnB[lane][w] = m0 + m1;
        __syncthreads();
        float4 va = *(const float4*)pnA[lane];
        float4 vb = *(const float4*)pnB[lane];
        na = (va.x + va.y) + (va.z + va.w);
        nb = (vb.x + vb.y) + (vb.z + vb.w);
    }

    // weight = log(lambda)/lambda^2 with lambda^2 = |g|^2
    float wa = 0.5f * logf(fmaxf(na, 1e-30f)) / na;
    float wb = 0.5f * logf(fmaxf(nb, 1e-30f)) / nb;

    // stash columns + per-column weights (warp 0 writes wcol; replicated)
    {
        const int ia = 2 * lane, ib = 2 * lane + 1;
        #pragma unroll
        for (int k = 0; k < 16; ++k) {
            int r = 16 * w + k;
            Gsm[r * DQ + ia] = a[k];
            Gsm[r * DQ + ib] = b[k];
        }
        if (w == 0) { wcol[ia] = wa; wcol[ib] = wb; }
    }
    __syncthreads();

    // L[r,c] = sum_col wcol[col]*G[r,col]*G[c,col]
    // 128 threads: 2 per row; each owns a 32-column half of the output row.
    const int r  = tid >> 1;
    const int c0 = (tid & 1) * 32;

    float hrow[64];
    #pragma unroll
    for (int t = 0; t < 16; ++t) {
        float4 g4 = *(const float4*)&Gsm[r * DQ + 4 * t];
        float4 w4 = *(const float4*)&wcol[4 * t];
        hrow[4*t+0] = g4.x * w4.x; hrow[4*t+1] = g4.y * w4.y;
        hrow[4*t+2] = g4.z * w4.z; hrow[4*t+3] = g4.w * w4.w;
    }

    float ssum = 0.f, sqsum = 0.f;
    float* orow = g_L + (size_t)m * DD + r * D + c0;
    for (int c4 = 0; c4 < 32; c4 += 4) {
        float acc[4] = {0.f, 0.f, 0.f, 0.f};
        #pragma unroll
        for (int cc = 0; cc < 4; ++cc) {
            const int c = c0 + c4 + cc;
            #pragma unroll
            for (int t = 0; t < 16; ++t) {
                float4 g = *(const float4*)&Gsm[c * DQ + 4 * t];
                acc[cc] = fmaf(hrow[4*t+0], g.x, acc[cc]);
                acc[cc] = fmaf(hrow[4*t+1], g.y, acc[cc]);
                acc[cc] = fmaf(hrow[4*t+2], g.z, acc[cc]);
                acc[cc] = fmaf(hrow[4*t+3], g.w, acc[cc]);
            }
        }
        *(float4*)&orow[c4] = make_float4(acc[0], acc[1], acc[2], acc[3]);
        #pragma unroll
        for (int cc = 0; cc < 4; ++cc) {
            ssum += acc[cc];
            sqsum = fmaf(acc[cc], acc[cc], sqsum);
        }
    }
    #pragma unroll
    for (int o = 16; o; o >>= 1) {
        ssum  += __shfl_down_sync(FULL, ssum,  o);
        sqsum += __shfl_down_sync(FULL, sqsum, o);
    }
    if (lane == 0) { reds[w] = ssum; redq[w] = sqsum; }
    __syncthreads();
    if (tid == 0) {
        g_s[m]  = (reds[0] + reds[1]) + (reds[2] + reds[3]);
        g_sq[m] = (redq[0] + redq[1]) + (redq[2] + redq[3]);
    }
}

// ========================================================================
// Kernel 2: gram partials  g_gp[z][i][j] = sum_{k in z-chunk} L[i][k] L[j][k]
// ========================================================================
__global__ __launch_bounds__(256) void gram_kernel() {
    __shared__ float As[64 * 17];
    __shared__ float Bs[64 * 17];
    const int bj = blockIdx.x, bi = blockIdx.y, bz = blockIdx.z;
    const int tid = threadIdx.x;
    const int ty = tid >> 4, tx = tid & 15;

    float acc[4][4];
    #pragma unroll
    for (int r = 0; r < 4; ++r)
        #pragma unroll
        for (int c = 0; c < 4; ++c) acc[r][c] = 0.0f;

    const int k0 = bz * 512;
    for (int kc = 0; kc < 512; kc += 16) {
        for (int l = tid; l < 1024; l += 256) {
            int r = l >> 4, kk = l & 15;
            As[r * 17 + kk] = g_L[(size_t)(bi * 64 + r) * DD + k0 + kc + kk];
            Bs[r * 17 + kk] = g_L[(size_t)(bj * 64 + r) * DD + k0 + kc + kk];
        }
        __syncthreads();
        #pragma unroll
        for (int kk = 0; kk < 16; ++kk) {
            float a[4], b[4];
            #pragma unroll
            for (int r = 0; r < 4; ++r) a[r] = As[(ty * 4 + r) * 17 + kk];
            #pragma unroll
            for (int c = 0; c < 4; ++c) b[c] = Bs[(tx * 4 + c) * 17 + kk];
            #pragma unroll
            for (int r = 0; r < 4; ++r)
                #pragma unroll
                for (int c = 0; c < 4; ++c)
                    acc[r][c] = fmaf(a[r], b[c], acc[r][c]);
        }
        __syncthreads();
    }
    #pragma unroll
    for (int r = 0; r < 4; ++r)
        #pragma unroll
        for (int c = 0; c < 4; ++c)
            g_gp[((size_t)bz * NMAT + bi * 64 + ty * 4 + r) * NMAT + bj * 64 + tx * 4 + c] = acc[r][c];
}

// ========================================================================
// Kernel 3: W = exp(-0.5 * pds / bw^2), fused row sums.  block = row i
// ========================================================================
__global__ __launch_bounds__(256) void w_kernel(const float* __restrict__ bwp) {
    __shared__ float red[8];
    const int i = blockIdx.x;
    const int j = threadIdx.x;

    float g = 0.0f;
    #pragma unroll
    for (int z = 0; z < 8; ++z)
        g += g_gp[((size_t)z * NMAT + i) * NMAT + j];

    const float bw  = bwp[0];
    const float inv = 0.5f / (bw * bw);
    const float eps = 1e-7f;
    float pds = g_sq[i] + g_sq[j] - 2.0f * g
              + 2.0f * eps * (g_s[j] - g_s[i])
              + eps * eps * 4096.0f;
    float wv = expf(-pds * inv);
    g_W[i * NMAT + j] = wv;

    float sum = wv;
    #pragma unroll
    for (int o = 16; o; o >>= 1) sum += __shfl_down_sync(0xffffffffu, sum, o);
    if ((j & 31) == 0) red[j >> 5] = sum;
    __syncthreads();
    if (j == 0) {
        float t = 0.0f;
        #pragma unroll
        for (int w = 0; w < 8; ++w) t += red[w];
        g_rs[i] = t;
    }
}

// col sums: 8 blocks x 256 threads, coalesced
__global__ __launch_bounds__(256) void colsum_kernel() {
    __shared__ float part[8][32];
    const int c0 = blockIdx.x * 32;
    const int c = threadIdx.x & 31;
    const int rchunk = threadIdx.x >> 5;
    float s = 0.0f;
    #pragma unroll
    for (int rr = 0; rr < 32; ++rr)
        s += g_W[(rchunk * 32 + rr) * NMAT + c0 + c];
    part[rchunk][c] = s;
    __syncthreads();
    if (threadIdx.x < 32) {
        float t = 0.0f;
        #pragma unroll
        for (int w = 0; w < 8; ++w) t += part[w][threadIdx.x];
        g_cs[c0 + threadIdx.x] = t;
    }
}

// ========================================================================
// Kernel 4: C = W^T L, fused mean-shift epilogue -> S = L_k + (C - cs_k L_k)/rs_k
// ========================================================================
__global__ __launch_bounds__(256) void ms_kernel() {
    __shared__ float Wt[16 * 65];
    __shared__ float Lt[16 * 65];
    const int bc = blockIdx.x;   // column tile
    const int bk = blockIdx.y;   // k (output row) tile
    const int tid = threadIdx.x;
    const int ty = tid >> 4, tx = tid & 15;

    float acc[4][4];
    #pragma unroll
    for (int r = 0; r < 4; ++r)
        #pragma unroll
        for (int c = 0; c < 4; ++c) acc[r][c] = 0.0f;

    for (int j0 = 0; j0 < NMAT; j0 += 16) {
        for (int l = tid; l < 1024; l += 256) {
            int jj = l >> 6, c = l & 63;
            Wt[jj * 65 + c] = g_W[(j0 + jj) * NMAT + bk * 64 + c];
            Lt[jj * 65 + c] = g_L[(size_t)(j0 + jj) * DD + bc * 64 + c];
        }
        __syncthreads();
        #pragma unroll
        for (int jj = 0; jj < 16; ++jj) {
            float a[4], b[4];
            #pragma unroll
            for (int r = 0; r < 4; ++r) a[r] = Wt[jj * 65 + ty * 4 + r];
            #pragma unroll
            for (int c = 0; c < 4; ++c) b[c] = Lt[jj * 65 + tx * 4 + c];
            #pragma unroll
            for (int r = 0; r < 4; ++r)
                #pragma unroll
                for (int c = 0; c < 4; ++c)
                    acc[r][c] = fmaf(a[r], b[c], acc[r][c]);
        }
        __syncthreads();
    }
    #pragma unroll
    for (int r = 0; r < 4; ++r) {
        int k = bk * 64 + ty * 4 + r;
        float rs = g_rs[k], cs = g_cs[k];
        float inv_rs = 1.0f / rs;
        #pragma unroll
        for (int c = 0; c < 4; ++c) {
            int col = bc * 64 + tx * 4 + c;
            float lk = g_L[(size_t)k * DD + col];
            g_S[(size_t)k * DD + col] = lk + (acc[r][c] - cs * lk) * inv_rs;
        }
    }
}

// ========================================================================
// Kernel 5: expm(S), scaling-and-squaring + order-8 Horner (first step folded
//   into init). 128 threads: 2 threads per row, each owns a 32-column half.
// ========================================================================
__global__ __launch_bounds__(128) void expm_kernel(float* __restrict__ out) {
    __shared__ float Q[D * DQ];
    __shared__ float redw[4];

    const int m   = blockIdx.x;
    const int tid = threadIdx.x;
    const int i   = tid >> 1;          // row
    const int c0  = (tid & 1) * 32;    // column half base

    // full B row straight from gmem (both half-threads load the same row)
    float brow[64];
    {
        const float4* sr = (const float4*)(g_S + (size_t)m * DD + i * D);
        #pragma unroll
        for (int t = 0; t < 16; ++t) {
            float4 v = sr[t];
            brow[4*t+0] = v.x; brow[4*t+1] = v.y;
            brow[4*t+2] = v.z; brow[4*t+3] = v.w;
        }
    }

    // Frobenius norm: each thread contributes its own half's squares (exact cover)
    float local = 0.0f;
    #pragma unroll
    for (int k = 0; k < 32; ++k) local = fmaf(brow[c0 + k], brow[c0 + k], local);
    #pragma unroll
    for (int o = 16; o; o >>= 1) local += __shfl_down_sync(0xffffffffu, local, o);
    if ((tid & 31) == 0) redw[tid >> 5] = local;
    __syncthreads();

    float nf = sqrtf((redw[0] + redw[1]) + (redw[2] + redw[3]));
    int ksc = 0;
    if (nf > 0.5f) {
        ksc = (int)ceilf(log2f(nf * 2.0f));
        if (ksc > 15) ksc = 15;
        if (ksc < 0)  ksc = 0;
    }
    const float sc = exp2f((float)(-ksc));
    #pragma unroll
    for (int k = 0; k < 64; ++k) brow[k] *= sc;

    // init Q = I + B/8 (folds first Horner step; order 8 total)
    {
        const float i8 = 1.0f / 8.0f;
        #pragma unroll
        for (int t = 0; t < 8; ++t) {
            int c = c0 + 4 * t;
            float4 o4 = make_float4(
                brow[c+0] * i8 + ((c+0 == i) ? 1.f : 0.f),
                brow[c+1] * i8 + ((c+1 == i) ? 1.f : 0.f),
                brow[c+2] * i8 + ((c+2 == i) ? 1.f : 0.f),
                brow[c+3] * i8 + ((c+3 == i) ? 1.f : 0.f));
            *(float4*)&Q[i * DQ + c] = o4;
        }
    }
    __syncthreads();

    float rrow[32];

    // Horner: Q_{n-1} = I + (B * Q_n)/n, n = 7..1
    for (int n = 7; n >= 1; --n) {
        #pragma unroll
        for (int j = 0; j < 32; ++j) rrow[j] = 0.0f;
        for (int k = 0; k < D; ++k) {
            float bv = brow[k];
            #pragma unroll
            for (int t = 0; t < 8; ++t) {
                float4 q = *(const float4*)&Q[k * DQ + c0 + 4 * t];
                rrow[4*t+0] = fmaf(bv, q.x, rrow[4*t+0]);
                rrow[4*t+1] = fmaf(bv, q.y, rrow[4*t+1]);
                rrow[4*t+2] = fmaf(bv, q.z, rrow[4*t+2]);
                rrow[4*t+3] = fmaf(bv, q.w, rrow[4*t+3]);
            }
        }
        __syncthreads();
        const float invn = 1.0f / (float)n;
        #pragma unroll
        for (int t = 0; t < 8; ++t) {
            int c = c0 + 4 * t;
            float4 o4 = make_float4(
                rrow[4*t+0] * invn + ((c+0 == i) ? 1.f : 0.f),
                rrow[4*t+1] * invn + ((c+1 == i) ? 1.f : 0.f),
                rrow[4*t+2] * invn + ((c+2 == i) ? 1.f : 0.f),
                rrow[4*t+3] * invn + ((c+3 == i) ? 1.f : 0.f));
            *(float4*)&Q[i * DQ + c] = o4;
        }
        __syncthreads();
    }

    // repeated squaring (ksc uniform across the block)
    for (int t2 = 0; t2 < ksc; ++t2) {
        #pragma unroll
        for (int t = 0; t < 16; ++t) {
            float4 v = *(const float4*)&Q[i * DQ + 4 * t];
            brow[4*t+0] = v.x; brow[4*t+1] = v.y; brow[4*t+2] = v.z; brow[4*t+3] = v.w;
        }
        #pragma unroll
        for (int j = 0; j < 32; ++j) rrow[j] = 0.0f;
        for (int k = 0; k < D; ++k) {
            float bv = brow[k];
            #pragma unroll
            for (int t = 0; t < 8; ++t) {
                float4 q = *(const float4*)&Q[k * DQ + c0 + 4 * t];
                rrow[4*t+0] = fmaf(bv, q.x, rrow[4*t+0]);
                rrow[4*t+1] = fmaf(bv, q.y, rrow[4*t+1]);
                rrow[4*t+2] = fmaf(bv, q.z, rrow[4*t+2]);
                rrow[4*t+3] = fmaf(bv, q.w, rrow[4*t+3]);
            }
        }
        __syncthreads();
        #pragma unroll
        for (int t = 0; t < 8; ++t)
            *(float4*)&Q[i * DQ + c0 + 4 * t] =
                make_float4(rrow[4*t+0], rrow[4*t+1], rrow[4*t+2], rrow[4*t+3]);
        __syncthreads();
    }

    float* om = out + (size_t)m * DD + i * D + c0;
    #pragma unroll
    for (int t = 0; t < 8; ++t) {
        float4 v = *(const float4*)&Q[i * DQ + c0 + 4 * t];
        *(float4*)&om[4 * t] = v;
    }
}

// ========================================================================
extern "C" void kernel_launch(void* const* d_in, const int* in_sizes, int n_in,
                              void* d_out, int out_size) {
    const float* X  = (const float*)d_in[0];
    const float* bw = (const float*)d_in[1];
    float* out = (float*)d_out;

    onesided_log_kernel<<<NMAT, 128>>>(X);
    gram_kernel<<<dim3(4, 4, 8), 256>>>();
    w_kernel<<<NMAT, 256>>>(bw);
    colsum_kernel<<<8, 256>>>();
    ms_kernel<<<dim3(64, 4), 256>>>();
    expm_kernel<<<NMAT, 128>>>(out);
}